// round 16
// baseline (speedup 1.0000x reference)
#include <cuda_runtime.h>
#include <cuda_fp16.h>
#include <math.h>
#include <cstdint>

#define S_LEN   2048
#define HIDDEN  2048
#define HEADS   32
#define HD      128
#define QKV_N   (3 * HEADS * HD)   // 12288
#define OD      (HEADS * HD)       // 4096

// ---------------- scratch ---------------------------------------------------
__device__ float  g_qkv[(size_t)S_LEN * QKV_N];
__device__ float  g_rope[(size_t)S_LEN * HD];   // [s][0:64]=cos, [s][64:128]=sin
#define HSZ ((size_t)HEADS * S_LEN * HD)
__device__ __half g_qh[HSZ], g_ql[HSZ];
__device__ __half g_kh[HSZ];
__device__ __half g_vh[HSZ];
__device__ __half g_oh[(size_t)S_LEN * OD];
__device__ __half g_hh[(size_t)S_LEN * HIDDEN];
__device__ __half g_wq[(size_t)QKV_N * HIDDEN];
__device__ __half g_wo[(size_t)HIDDEN * OD];

// ---------------- helpers ----------------------------------------------------
__device__ __forceinline__ uint32_t smem_u32(const void* p) {
    uint32_t a;
    asm("{ .reg .u64 t; cvta.to.shared.u64 t, %1; cvt.u32.u64 %0, t; }" : "=r"(a) : "l"(p));
    return a;
}
__device__ __forceinline__ uint32_t pack_h2(float a, float b) {
    __half2 h = __floats2half2_rn(a, b);
    return *reinterpret_cast<uint32_t*>(&h);
}
__device__ __forceinline__ void mma_f16(float* d, const uint32_t* a,
                                        uint32_t b0, uint32_t b1) {
    asm volatile(
        "mma.sync.aligned.m16n8k16.row.col.f32.f16.f16.f32 "
        "{%0,%1,%2,%3}, {%4,%5,%6,%7}, {%8,%9}, {%0,%1,%2,%3};"
        : "+f"(d[0]), "+f"(d[1]), "+f"(d[2]), "+f"(d[3])
        : "r"(a[0]), "r"(a[1]), "r"(a[2]), "r"(a[3]), "r"(b0), "r"(b1));
}
__device__ __forceinline__ void ldsm_x4(uint32_t* r, uint32_t addr) {
    asm volatile("ldmatrix.sync.aligned.m8n8.x4.shared.b16 {%0,%1,%2,%3}, [%4];"
        : "=r"(r[0]), "=r"(r[1]), "=r"(r[2]), "=r"(r[3]) : "r"(addr));
}
__device__ __forceinline__ void ldsm_x4_t(uint32_t* r, uint32_t addr) {
    asm volatile("ldmatrix.sync.aligned.m8n8.x4.trans.shared.b16 {%0,%1,%2,%3}, [%4];"
        : "=r"(r[0]), "=r"(r[1]), "=r"(r[2]), "=r"(r[3]) : "r"(addr));
}
__device__ __forceinline__ void cp16(uint32_t s, const void* g) {
    asm volatile("cp.async.cg.shared.global [%0], [%1], 16;" :: "r"(s), "l"(g));
}
__device__ __forceinline__ void cp_commit() {
    asm volatile("cp.async.commit_group;" ::: "memory");
}
template <int N> __device__ __forceinline__ void cp_wait() {
    asm volatile("cp.async.wait_group %0;" :: "n"(N) : "memory");
}

// ---------------- fp32 -> fp16 streaming convert -----------------------------
__global__ __launch_bounds__(256) void f2h(const float* __restrict__ x,
                                           __half* __restrict__ y, int n)
{
    int i = (blockIdx.x * 256 + threadIdx.x) * 4;
    if (i < n) {
        float4 v = *(const float4*)&x[i];
        uint2 p = make_uint2(pack_h2(v.x, v.y), pack_h2(v.z, v.w));
        *(uint2*)&y[i] = p;
    }
}

// ---------------- half-input HMMA GEMM NT (unchanged from R13) ---------------
#define GBK   64
#define GARR  16384
#define GSLOT (2 * GARR)
#define GEMMH_SMEM (3 * GSLOT)      // 98304

__global__ __launch_bounds__(256, 2) void gemm_h(const __half* __restrict__ A,
                                                 const __half* __restrict__ B,
                                                 float* __restrict__ C,
                                                 int M, int N, int K)
{
    extern __shared__ char gsm[];
    const uint32_t smb = smem_u32(gsm);

    const int tid  = threadIdx.x;
    const int wid  = tid >> 5;
    const int l    = tid & 31;
    const int g    = l >> 2;
    const int t    = l & 3;
    const int wm   = (wid >> 2) * 64;
    const int wn   = (wid & 3) * 32;
    const int bm0  = blockIdx.y * 128;
    const int bn0  = blockIdx.x * 128;

    const int cr  = tid >> 1;
    const int cb4 = (tid & 1) * 4;
    const __half* arow = A + (size_t)(bm0 + cr) * K;
    const __half* brow = B + (size_t)(bn0 + cr) * K;

    const int frag = (l & 7) + 8 * ((l >> 3) & 1);
    const int cl   = l >> 4;
    const int kr   = (l & 7) + 8 * (l >> 4);
    const int kcl  = (l >> 3) & 1;

    const int nkt = K / GBK;

#pragma unroll
    for (int tl = 0; tl < 2; tl++) {
        uint32_t sl = smb + tl * GSLOT;
#pragma unroll
        for (int i = 0; i < 4; i++) {
            int c  = cb4 + i;
            int sw = ((c ^ (cr & 7)) * 16);
            cp16(sl + cr * 128 + sw,        arow + tl * GBK + c * 8);
            cp16(sl + GARR + cr * 128 + sw, brow + tl * GBK + c * 8);
        }
        cp_commit();
    }

    float acc[4][4][4];
#pragma unroll
    for (int i = 0; i < 4; i++)
#pragma unroll
        for (int j = 0; j < 4; j++)
#pragma unroll
            for (int r = 0; r < 4; r++) acc[i][j][r] = 0.f;

    for (int kt = 0; kt < nkt; kt++) {
        cp_wait<1>();
        __syncthreads();

        if (kt + 2 < nkt) {
            uint32_t sl = smb + ((kt + 2) % 3) * GSLOT;
#pragma unroll
            for (int i = 0; i < 4; i++) {
                int c  = cb4 + i;
                int sw = ((c ^ (cr & 7)) * 16);
                cp16(sl + cr * 128 + sw,        arow + (kt + 2) * GBK + c * 8);
                cp16(sl + GARR + cr * 128 + sw, brow + (kt + 2) * GBK + c * 8);
            }
            cp_commit();
        } else {
            cp_commit();
        }

        const uint32_t sl = smb + (kt % 3) * GSLOT;
#pragma unroll
        for (int ks = 0; ks < 4; ks++) {
            uint32_t af[4][4];
#pragma unroll
            for (int mt = 0; mt < 4; mt++)
                ldsm_x4(af[mt], sl + (wm + mt * 16 + frag) * 128
                                  + (((2 * ks + cl) ^ (frag & 7)) * 16));
#pragma unroll
            for (int np = 0; np < 2; np++) {
                uint32_t bf[4];
                ldsm_x4(bf, sl + GARR + (wn + np * 16 + kr) * 128
                              + (((2 * ks + kcl) ^ (kr & 7)) * 16));
#pragma unroll
                for (int mt = 0; mt < 4; mt++) {
                    mma_f16(acc[mt][2 * np],     af[mt], bf[0], bf[1]);
                    mma_f16(acc[mt][2 * np + 1], af[mt], bf[2], bf[3]);
                }
            }
        }
    }

#pragma unroll
    for (int mt = 0; mt < 4; mt++) {
        int row0 = bm0 + wm + mt * 16 + g;
#pragma unroll
        for (int nt = 0; nt < 4; nt++) {
            int col = bn0 + wn + nt * 8 + 2 * t;
            *(float2*)&C[(size_t)row0 * N + col] = make_float2(acc[mt][nt][0], acc[mt][nt][1]);
            *(float2*)&C[(size_t)(row0 + 8) * N + col] = make_float2(acc[mt][nt][2], acc[mt][nt][3]);
        }
    }
}

// ---------------- RoPE cos/sin table -----------------------------------------
__global__ __launch_bounds__(64) void rope_table(const int* __restrict__ positions)
{
    const int s = blockIdx.x;
    const int d = threadIdx.x;
    float inv = expf(-9.210340371976184f * (float)(2 * d) * (1.0f / HD));
    float ang = (float)positions[s] * inv;
    float c, sn;
    sincosf(ang, &sn, &c);
    g_rope[(size_t)s * HD + d]      = c;
    g_rope[(size_t)s * HD + 64 + d] = sn;
}

// ---------------- RMSNorm + RoPE (table) + hi/lo scatter ---------------------
__device__ __forceinline__ void split_store(__half* ph, __half* pl, size_t i, float x) {
    __half h = __float2half_rn(x);
    ph[i] = h;
    pl[i] = __float2half_rn(x - __half2float(h));
}

__global__ __launch_bounds__(128) void norm_rope(const float* __restrict__ qkv,
                                                 const float* __restrict__ qw,
                                                 const float* __restrict__ kw)
{
    const int h = blockIdx.x;
    const int s = blockIdx.y;
    const int d = threadIdx.x;

    const float* base = qkv + (size_t)s * QKV_N + h * HD;
    float qv = base[d];
    float kv = base[HEADS * HD + d];
    float vv = base[2 * HEADS * HD + d];

    float q2 = qv * qv, k2 = kv * kv;
#pragma unroll
    for (int off = 16; off > 0; off >>= 1) {
        q2 += __shfl_xor_sync(0xffffffffu, q2, off);
        k2 += __shfl_xor_sync(0xffffffffu, k2, off);
    }
    __shared__ float sq[4], sk[4];
    int wid = d >> 5, lane = d & 31;
    if (lane == 0) { sq[wid] = q2; sk[wid] = k2; }
    __syncthreads();
    q2 = sq[0] + sq[1] + sq[2] + sq[3];
    k2 = sk[0] + sk[1] + sk[2] + sk[3];

    float qn = qv * rsqrtf(q2 * (1.f / HD) + 1e-5f) * qw[d];
    float kn = kv * rsqrtf(k2 * (1.f / HD) + 1e-5f) * kw[d];

    __shared__ float qs[HD], ks[HD];
    qs[d] = qn; ks[d] = kn;
    __syncthreads();

    const size_t out = ((size_t)h * S_LEN + s) * HD;
    g_vh[out + d] = __float2half_rn(vv);

    if (d < HD / 2) {
        float c  = g_rope[(size_t)s * HD + d];
        float sn = g_rope[(size_t)s * HD + 64 + d];

        float q1 = qs[d], q2v = qs[d + HD / 2];
        float k1 = ks[d], k2v = ks[d + HD / 2];
        split_store(g_qh, g_ql, out + d,          q1 * c - q2v * sn);
        split_store(g_qh, g_ql, out + d + HD / 2, q2v * c + q1 * sn);
        g_kh[out + d]          = __float2half_rn(k1 * c - k2v * sn);
        g_kh[out + d + HD / 2] = __float2half_rn(k2v * c + k1 * sn);
    }
}

// ---------------- tensor-core flash attention, BK=128 ------------------------
// BQ=128, BK=128, 256 threads. 2-slot cp.async double buffer (Kh|Vh).
// One softmax pass per 128 K-columns; exp2 with folded scale.
#define BQ   128
#define BK   128
#define HDP  136
#define ARRB (BK * HDP * 2)            // 34816 bytes per array
#define BUFB (2 * ARRB)                // 69632 per slot (Kh | Vh)
#define QB_BYTES (2 * BQ * HDP * 2)    // 69632 (Qh | Ql)
#define ATTN_SMEM (QB_BYTES + 2 * BUFB)  // 208896

__global__ __launch_bounds__(256) void attn_mma(const __half* __restrict__ qh,
                                                const __half* __restrict__ ql,
                                                const __half* __restrict__ kh,
                                                const __half* __restrict__ vh,
                                                __half* __restrict__ go)
{
    extern __shared__ __half sh[];
    __half* Qh = sh;
    __half* Ql = Qh + BQ * HDP;

    const int tid = threadIdx.x;
    const int wq  = tid >> 5;
    const int l   = tid & 31;
    const int t   = l & 3;
    const int g   = l >> 2;
    const int qb  = gridDim.x - 1 - blockIdx.x;   // heavy blocks first
    const int h   = blockIdx.y;
    const int rb  = wq * 16;
    const float CEXP = 0.08838834764831845f * 1.4426950408889634f; // scale*log2e

    const uint32_t smb  = smem_u32(sh);
    const uint32_t bufb = smb + QB_BYTES;
    const size_t hbase  = (size_t)h * S_LEN * HD;

    // ---- Q hi/lo tile ----
    const size_t qoff = hbase + (size_t)qb * BQ * HD;
    for (int idx = tid; idx < BQ * HD / 8; idx += 256) {
        int r = idx >> 4, c = (idx & 15) * 8;
        *(uint4*)&Qh[r * HDP + c] = *(const uint4*)&qh[qoff + r * HD + c];
        *(uint4*)&Ql[r * HDP + c] = *(const uint4*)&ql[qoff + r * HD + c];
    }

    // cp.async mapping: 2 threads per row, 8 chunks each
    const int cr = tid >> 1;
    const int c8 = (tid & 1) * 8;

    const int nkt = qb + 1;

    // preload tile 0 into slot 0
    {
        const size_t gk = hbase;
        const uint32_t db = bufb;
#pragma unroll
        for (int i = 0; i < 8; i++) {
            int c = c8 + i;
            uint32_t d0 = db + (uint32_t)(cr * HDP + c * 8) * 2;
            cp16(d0,        &kh[gk + cr * HD + c * 8]);
            cp16(d0 + ARRB, &vh[gk + cr * HD + c * 8]);
        }
        cp_commit();
    }

    float oacc[16][4];
#pragma unroll
    for (int i = 0; i < 16; i++)
#pragma unroll
        for (int j = 0; j < 4; j++) oacc[i][j] = 0.f;
    float m_a = -1e30f, m_b = -1e30f, l_a = 0.f, l_b = 0.f;

    // lane geometry
    const int frag  = (l & 7) + 8 * ((l >> 3) & 1);
    const int qvoff = frag * HDP + 8 * (l >> 4);
    const int koff  = ((l & 7) + 8 * (l >> 4)) * HDP + 8 * ((l >> 3) & 1);
    const uint32_t aQh = smb + (uint32_t)(rb * HDP + qvoff) * 2;
    const uint32_t aQl = aQh + BQ * HDP * 2;

    const int row_a = qb * BQ + rb + g;
    const int row_b = row_a + 8;
    const int row_max = qb * BQ + rb + 15;

    for (int kt = 0; kt < nkt; kt++) {
        // slot-guard: all warps done reading slot (kt+1)%2 (tile kt-1)
        __syncthreads();
        // prefetch tile kt+1 into slot (kt+1)%2
        if (kt + 1 < nkt) {
            const size_t gk = hbase + (size_t)(kt + 1) * BK * HD;
            const uint32_t db = bufb + (uint32_t)((kt + 1) & 1) * BUFB;
#pragma unroll
            for (int i = 0; i < 8; i++) {
                int c = c8 + i;
                uint32_t d0 = db + (uint32_t)(cr * HDP + c * 8) * 2;
                cp16(d0,        &kh[gk + cr * HD + c * 8]);
                cp16(d0 + ARRB, &vh[gk + cr * HD + c * 8]);
            }
            cp_commit();
        } else {
            cp_commit();
        }
        cp_wait<1>();      // tile kt landed (kt+1 in flight)
        __syncthreads();   // visibility of all threads' cp.async

        if (kt * BK <= row_max) {
            const uint32_t cb0 = bufb + (uint32_t)(kt & 1) * BUFB;
            const uint32_t aKh = cb0 + (uint32_t)koff * 2;
            const uint32_t aVh = cb0 + ARRB + (uint32_t)qvoff * 2;

            // ---- S = Q K^T : hi*hi + lo*hi over 128 K-rows ----
            float sacc[16][4];
#pragma unroll
            for (int i = 0; i < 16; i++)
#pragma unroll
                for (int j = 0; j < 4; j++) sacc[i][j] = 0.f;

#pragma unroll
            for (int ks = 0; ks < 8; ks++) {
                uint32_t qhf[4], qlf[4];
                ldsm_x4(qhf, aQh + ks * 32);
                ldsm_x4(qlf, aQl + ks * 32);
#pragma unroll
                for (int np = 0; np < 8; np++) {
                    uint32_t khf[4];
                    ldsm_x4(khf, aKh + np * (16 * HDP * 2) + ks * 32);
                    mma_f16(sacc[2 * np],     qhf, khf[0], khf[1]);
                    mma_f16(sacc[2 * np + 1], qhf, khf[2], khf[3]);
                    mma_f16(sacc[2 * np],     qlf, khf[0], khf[1]);
                    mma_f16(sacc[2 * np + 1], qlf, khf[2], khf[3]);
                }
            }

            // ---- causal mask + online softmax (raw domain, exp2 folded) ----
            float mx_a = -1e30f, mx_b = -1e30f;
#pragma unroll
            for (int nt = 0; nt < 16; nt++) {
                int c0 = kt * BK + nt * 8 + 2 * t, c1 = c0 + 1;
                float s0 = sacc[nt][0]; if (c0 > row_a) s0 = -1e30f;
                float s1 = sacc[nt][1]; if (c1 > row_a) s1 = -1e30f;
                float s2 = sacc[nt][2]; if (c0 > row_b) s2 = -1e30f;
                float s3 = sacc[nt][3]; if (c1 > row_b) s3 = -1e30f;
                sacc[nt][0] = s0; sacc[nt][1] = s1; sacc[nt][2] = s2; sacc[nt][3] = s3;
                mx_a = fmaxf(mx_a, fmaxf(s0, s1));
                mx_b = fmaxf(mx_b, fmaxf(s2, s3));
            }
            mx_a = fmaxf(mx_a, __shfl_xor_sync(0xffffffffu, mx_a, 1));
            mx_a = fmaxf(mx_a, __shfl_xor_sync(0xffffffffu, mx_a, 2));
            mx_b = fmaxf(mx_b, __shfl_xor_sync(0xffffffffu, mx_b, 1));
            mx_b = fmaxf(mx_b, __shfl_xor_sync(0xffffffffu, mx_b, 2));

            float mn_a = fmaxf(m_a, mx_a), mn_b = fmaxf(m_b, mx_b);
            float ca = exp2f((m_a - mn_a) * CEXP), cb2 = exp2f((m_b - mn_b) * CEXP);
            m_a = mn_a; m_b = mn_b;

            float sum_a = 0.f, sum_b = 0.f;
            uint32_t pah[8][4];
#pragma unroll
            for (int nt = 0; nt < 16; nt++) {
                float p0 = exp2f((sacc[nt][0] - mn_a) * CEXP);
                float p1 = exp2f((sacc[nt][1] - mn_a) * CEXP);
                float p2 = exp2f((sacc[nt][2] - mn_b) * CEXP);
                float p3 = exp2f((sacc[nt][3] - mn_b) * CEXP);
                sum_a += p0 + p1; sum_b += p2 + p3;
                int ks = nt >> 1, sel = (nt & 1) * 2;
                pah[ks][sel + 0] = pack_h2(p0, p1);
                pah[ks][sel + 1] = pack_h2(p2, p3);
            }
            sum_a += __shfl_xor_sync(0xffffffffu, sum_a, 1);
            sum_a += __shfl_xor_sync(0xffffffffu, sum_a, 2);
            sum_b += __shfl_xor_sync(0xffffffffu, sum_b, 1);
            sum_b += __shfl_xor_sync(0xffffffffu, sum_b, 2);
            l_a = l_a * ca + sum_a;
            l_b = l_b * cb2 + sum_b;

#pragma unroll
            for (int nt = 0; nt < 16; nt++) {
                oacc[nt][0] *= ca;  oacc[nt][1] *= ca;
                oacc[nt][2] *= cb2; oacc[nt][3] *= cb2;
            }

            // ---- O += P_hi * V_hi (128 K-rows) ----
#pragma unroll
            for (int ks = 0; ks < 8; ks++) {
#pragma unroll
                for (int np = 0; np < 8; np++) {
                    uint32_t vhf[4];
                    ldsm_x4_t(vhf, aVh + ks * (16 * HDP * 2) + np * 32);
                    mma_f16(oacc[2 * np],     pah[ks], vhf[0], vhf[1]);
                    mma_f16(oacc[2 * np + 1], pah[ks], vhf[2], vhf[3]);
                }
            }
        }
    }

    // ---- epilogue: half O out ----
    float ia = 1.f / l_a, ib = 1.f / l_b;
    __half* outa = go + (size_t)row_a * OD + h * HD;
    __half* outb = outa + (size_t)8 * OD;
#pragma unroll
    for (int nt = 0; nt < 16; nt++) {
        *(uint32_t*)&outa[nt * 8 + 2 * t] = pack_h2(oacc[nt][0] * ia, oacc[nt][1] * ia);
        *(uint32_t*)&outb[nt * 8 + 2 * t] = pack_h2(oacc[nt][2] * ib, oacc[nt][3] * ib);
    }
}

// ---------------- launch -----------------------------------------------------
extern "C" void kernel_launch(void* const* d_in, const int* in_sizes, int n_in,
                              void* d_out, int out_size)
{
    const float* hidden    = (const float*)d_in[0];
    const int*   positions = (const int*)  d_in[1];
    const float* qkv_w     = (const float*)d_in[2];
    const float* q_norm_w  = (const float*)d_in[3];
    const float* k_norm_w  = (const float*)d_in[4];
    const float* o_proj_w  = (const float*)d_in[5];
    float* out = (float*)d_out;

    float *p_qkv;
    __half *p_qh, *p_ql, *p_kh, *p_vh, *p_oh, *p_hh, *p_wq, *p_wo;
    cudaGetSymbolAddress((void**)&p_qkv, g_qkv);
    cudaGetSymbolAddress((void**)&p_qh,  g_qh);
    cudaGetSymbolAddress((void**)&p_ql,  g_ql);
    cudaGetSymbolAddress((void**)&p_kh,  g_kh);
    cudaGetSymbolAddress((void**)&p_vh,  g_vh);
    cudaGetSymbolAddress((void**)&p_oh,  g_oh);
    cudaGetSymbolAddress((void**)&p_hh,  g_hh);
    cudaGetSymbolAddress((void**)&p_wq,  g_wq);
    cudaGetSymbolAddress((void**)&p_wo,  g_wo);

    cudaFuncSetAttribute(attn_mma, cudaFuncAttributeMaxDynamicSharedMemorySize, ATTN_SMEM);
    cudaFuncSetAttribute(gemm_h,   cudaFuncAttributeMaxDynamicSharedMemorySize, GEMMH_SMEM);

    // 0) conversions + rope table
    {
        int n1 = S_LEN * HIDDEN;
        f2h<<<n1 / 1024, 256>>>(hidden, p_hh, n1);
        int n2 = QKV_N * HIDDEN;
        f2h<<<n2 / 1024, 256>>>(qkv_w, p_wq, n2);
        int n3 = HIDDEN * OD;
        f2h<<<n3 / 1024, 256>>>(o_proj_w, p_wo, n3);
        rope_table<<<S_LEN, 64>>>(positions);
    }

    // 1) QKV GEMM (half inputs)
    gemm_h<<<dim3(QKV_N / 128, S_LEN / 128), 256, GEMMH_SMEM>>>(p_hh, p_wq, p_qkv,
                                                                S_LEN, QKV_N, HIDDEN);

    // 2) RMSNorm + RoPE (table) + hi/lo scatter
    norm_rope<<<dim3(HEADS, S_LEN), 128>>>(p_qkv, q_norm_w, k_norm_w);

    // 3) tensor-core causal flash attention (BK=128)
    attn_mma<<<dim3(S_LEN / BQ, HEADS), 256, ATTN_SMEM>>>(p_qh, p_ql, p_kh, p_vh, p_oh);

    // 4) O projection (half inputs)
    gemm_h<<<dim3(HIDDEN / 128, S_LEN / 128), 256, GEMMH_SMEM>>>(p_oh, p_wo, out,
                                                                 S_LEN, HIDDEN, OD);
}

// round 17
// speedup vs baseline: 1.1095x; 1.1095x over previous
#include <cuda_runtime.h>
#include <cuda_fp16.h>
#include <math.h>
#include <cstdint>

#define S_LEN   2048
#define HIDDEN  2048
#define HEADS   32
#define HD      128
#define QKV_N   (3 * HEADS * HD)   // 12288
#define OD      (HEADS * HD)       // 4096

// ---------------- scratch ---------------------------------------------------
__device__ float  g_qkv[(size_t)S_LEN * QKV_N];
__device__ float  g_rope[(size_t)S_LEN * HD];   // [s][0:64]=cos, [s][64:128]=sin
#define HSZ ((size_t)HEADS * S_LEN * HD)
__device__ __half g_qh[HSZ];
__device__ __half g_kh[HSZ];
__device__ __half g_vh[HSZ];
__device__ __half g_oh[(size_t)S_LEN * OD];
__device__ __half g_hh[(size_t)S_LEN * HIDDEN];
__device__ __half g_wq[(size_t)QKV_N * HIDDEN];
__device__ __half g_wo[(size_t)HIDDEN * OD];

// ---------------- helpers ----------------------------------------------------
__device__ __forceinline__ uint32_t smem_u32(const void* p) {
    uint32_t a;
    asm("{ .reg .u64 t; cvta.to.shared.u64 t, %1; cvt.u32.u64 %0, t; }" : "=r"(a) : "l"(p));
    return a;
}
__device__ __forceinline__ uint32_t pack_h2(float a, float b) {
    __half2 h = __floats2half2_rn(a, b);
    return *reinterpret_cast<uint32_t*>(&h);
}
__device__ __forceinline__ void mma_f16(float* d, const uint32_t* a,
                                        uint32_t b0, uint32_t b1) {
    asm volatile(
        "mma.sync.aligned.m16n8k16.row.col.f32.f16.f16.f32 "
        "{%0,%1,%2,%3}, {%4,%5,%6,%7}, {%8,%9}, {%0,%1,%2,%3};"
        : "+f"(d[0]), "+f"(d[1]), "+f"(d[2]), "+f"(d[3])
        : "r"(a[0]), "r"(a[1]), "r"(a[2]), "r"(a[3]), "r"(b0), "r"(b1));
}
__device__ __forceinline__ void ldsm_x4(uint32_t* r, uint32_t addr) {
    asm volatile("ldmatrix.sync.aligned.m8n8.x4.shared.b16 {%0,%1,%2,%3}, [%4];"
        : "=r"(r[0]), "=r"(r[1]), "=r"(r[2]), "=r"(r[3]) : "r"(addr));
}
__device__ __forceinline__ void ldsm_x4_t(uint32_t* r, uint32_t addr) {
    asm volatile("ldmatrix.sync.aligned.m8n8.x4.trans.shared.b16 {%0,%1,%2,%3}, [%4];"
        : "=r"(r[0]), "=r"(r[1]), "=r"(r[2]), "=r"(r[3]) : "r"(addr));
}
__device__ __forceinline__ void cp16(uint32_t s, const void* g) {
    asm volatile("cp.async.cg.shared.global [%0], [%1], 16;" :: "r"(s), "l"(g));
}
__device__ __forceinline__ void cp_commit() {
    asm volatile("cp.async.commit_group;" ::: "memory");
}
template <int N> __device__ __forceinline__ void cp_wait() {
    asm volatile("cp.async.wait_group %0;" :: "n"(N) : "memory");
}

// ---------------- fp32 -> fp16 streaming convert -----------------------------
__global__ __launch_bounds__(256) void f2h(const float* __restrict__ x,
                                           __half* __restrict__ y, int n)
{
    int i = (blockIdx.x * 256 + threadIdx.x) * 4;
    if (i < n) {
        float4 v = *(const float4*)&x[i];
        uint2 p = make_uint2(pack_h2(v.x, v.y), pack_h2(v.z, v.w));
        *(uint2*)&y[i] = p;
    }
}

// ---------------- half-input HMMA GEMM NT (unchanged from R13) ---------------
#define GBK   64
#define GARR  16384
#define GSLOT (2 * GARR)
#define GEMMH_SMEM (3 * GSLOT)      // 98304

__global__ __launch_bounds__(256, 2) void gemm_h(const __half* __restrict__ A,
                                                 const __half* __restrict__ B,
                                                 float* __restrict__ C,
                                                 int M, int N, int K)
{
    extern __shared__ char gsm[];
    const uint32_t smb = smem_u32(gsm);

    const int tid  = threadIdx.x;
    const int wid  = tid >> 5;
    const int l    = tid & 31;
    const int g    = l >> 2;
    const int t    = l & 3;
    const int wm   = (wid >> 2) * 64;
    const int wn   = (wid & 3) * 32;
    const int bm0  = blockIdx.y * 128;
    const int bn0  = blockIdx.x * 128;

    const int cr  = tid >> 1;
    const int cb4 = (tid & 1) * 4;
    const __half* arow = A + (size_t)(bm0 + cr) * K;
    const __half* brow = B + (size_t)(bn0 + cr) * K;

    const int frag = (l & 7) + 8 * ((l >> 3) & 1);
    const int cl   = l >> 4;
    const int kr   = (l & 7) + 8 * (l >> 4);
    const int kcl  = (l >> 3) & 1;

    const int nkt = K / GBK;

#pragma unroll
    for (int tl = 0; tl < 2; tl++) {
        uint32_t sl = smb + tl * GSLOT;
#pragma unroll
        for (int i = 0; i < 4; i++) {
            int c  = cb4 + i;
            int sw = ((c ^ (cr & 7)) * 16);
            cp16(sl + cr * 128 + sw,        arow + tl * GBK + c * 8);
            cp16(sl + GARR + cr * 128 + sw, brow + tl * GBK + c * 8);
        }
        cp_commit();
    }

    float acc[4][4][4];
#pragma unroll
    for (int i = 0; i < 4; i++)
#pragma unroll
        for (int j = 0; j < 4; j++)
#pragma unroll
            for (int r = 0; r < 4; r++) acc[i][j][r] = 0.f;

    for (int kt = 0; kt < nkt; kt++) {
        cp_wait<1>();
        __syncthreads();

        if (kt + 2 < nkt) {
            uint32_t sl = smb + ((kt + 2) % 3) * GSLOT;
#pragma unroll
            for (int i = 0; i < 4; i++) {
                int c  = cb4 + i;
                int sw = ((c ^ (cr & 7)) * 16);
                cp16(sl + cr * 128 + sw,        arow + (kt + 2) * GBK + c * 8);
                cp16(sl + GARR + cr * 128 + sw, brow + (kt + 2) * GBK + c * 8);
            }
            cp_commit();
        } else {
            cp_commit();
        }

        const uint32_t sl = smb + (kt % 3) * GSLOT;
#pragma unroll
        for (int ks = 0; ks < 4; ks++) {
            uint32_t af[4][4];
#pragma unroll
            for (int mt = 0; mt < 4; mt++)
                ldsm_x4(af[mt], sl + (wm + mt * 16 + frag) * 128
                                  + (((2 * ks + cl) ^ (frag & 7)) * 16));
#pragma unroll
            for (int np = 0; np < 2; np++) {
                uint32_t bf[4];
                ldsm_x4(bf, sl + GARR + (wn + np * 16 + kr) * 128
                              + (((2 * ks + kcl) ^ (kr & 7)) * 16));
#pragma unroll
                for (int mt = 0; mt < 4; mt++) {
                    mma_f16(acc[mt][2 * np],     af[mt], bf[0], bf[1]);
                    mma_f16(acc[mt][2 * np + 1], af[mt], bf[2], bf[3]);
                }
            }
        }
    }

#pragma unroll
    for (int mt = 0; mt < 4; mt++) {
        int row0 = bm0 + wm + mt * 16 + g;
#pragma unroll
        for (int nt = 0; nt < 4; nt++) {
            int col = bn0 + wn + nt * 8 + 2 * t;
            *(float2*)&C[(size_t)row0 * N + col] = make_float2(acc[mt][nt][0], acc[mt][nt][1]);
            *(float2*)&C[(size_t)(row0 + 8) * N + col] = make_float2(acc[mt][nt][2], acc[mt][nt][3]);
        }
    }
}

// ---------------- RoPE cos/sin table -----------------------------------------
__global__ __launch_bounds__(64) void rope_table(const int* __restrict__ positions)
{
    const int s = blockIdx.x;
    const int d = threadIdx.x;
    float inv = expf(-9.210340371976184f * (float)(2 * d) * (1.0f / HD));
    float ang = (float)positions[s] * inv;
    float c, sn;
    sincosf(ang, &sn, &c);
    g_rope[(size_t)s * HD + d]      = c;
    g_rope[(size_t)s * HD + 64 + d] = sn;
}

// ---------------- RMSNorm + RoPE (table) + fp16 scatter ----------------------
__global__ __launch_bounds__(128) void norm_rope(const float* __restrict__ qkv,
                                                 const float* __restrict__ qw,
                                                 const float* __restrict__ kw)
{
    const int h = blockIdx.x;
    const int s = blockIdx.y;
    const int d = threadIdx.x;

    const float* base = qkv + (size_t)s * QKV_N + h * HD;
    float qv = base[d];
    float kv = base[HEADS * HD + d];
    float vv = base[2 * HEADS * HD + d];

    float q2 = qv * qv, k2 = kv * kv;
#pragma unroll
    for (int off = 16; off > 0; off >>= 1) {
        q2 += __shfl_xor_sync(0xffffffffu, q2, off);
        k2 += __shfl_xor_sync(0xffffffffu, k2, off);
    }
    __shared__ float sq[4], sk[4];
    int wid = d >> 5, lane = d & 31;
    if (lane == 0) { sq[wid] = q2; sk[wid] = k2; }
    __syncthreads();
    q2 = sq[0] + sq[1] + sq[2] + sq[3];
    k2 = sk[0] + sk[1] + sk[2] + sk[3];

    float qn = qv * rsqrtf(q2 * (1.f / HD) + 1e-5f) * qw[d];
    float kn = kv * rsqrtf(k2 * (1.f / HD) + 1e-5f) * kw[d];

    __shared__ float qs[HD], ks[HD];
    qs[d] = qn; ks[d] = kn;
    __syncthreads();

    const size_t out = ((size_t)h * S_LEN + s) * HD;
    g_vh[out + d] = __float2half_rn(vv);

    if (d < HD / 2) {
        float c  = g_rope[(size_t)s * HD + d];
        float sn = g_rope[(size_t)s * HD + 64 + d];

        float q1 = qs[d], q2v = qs[d + HD / 2];
        float k1 = ks[d], k2v = ks[d + HD / 2];
        g_qh[out + d]          = __float2half_rn(q1 * c - q2v * sn);
        g_qh[out + d + HD / 2] = __float2half_rn(q2v * c + q1 * sn);
        g_kh[out + d]          = __float2half_rn(k1 * c - k2v * sn);
        g_kh[out + d + HD / 2] = __float2half_rn(k2v * c + k1 * sn);
    }
}

// ---------------- tensor-core flash attention (R13 structure, 1-term QK) -----
#define BQ   128
#define BK   64
#define HDP  136
#define ARRB (BK * HDP * 2)
#define BUFB (2 * ARRB)
#define QB_BYTES (BQ * HDP * 2)        // 34816 (Qh only)
#define ATTN_SMEM (QB_BYTES + 3 * BUFB)  // 139264

__global__ __launch_bounds__(256) void attn_mma(const __half* __restrict__ qh,
                                                const __half* __restrict__ kh,
                                                const __half* __restrict__ vh,
                                                __half* __restrict__ go)
{
    extern __shared__ __half sh[];
    __half* Qh = sh;

    const int tid = threadIdx.x;
    const int wq  = tid >> 5;
    const int l   = tid & 31;
    const int t   = l & 3;
    const int g   = l >> 2;
    const int qb  = gridDim.x - 1 - blockIdx.x;
    const int h   = blockIdx.y;
    const int rb  = wq * 16;
    const float CEXP = 0.08838834764831845f * 1.4426950408889634f; // scale*log2e

    const uint32_t smb  = smem_u32(sh);
    const uint32_t bufb = smb + QB_BYTES;
    const size_t hbase  = (size_t)h * S_LEN * HD;

    const size_t qoff = hbase + (size_t)qb * BQ * HD;
    for (int idx = tid; idx < BQ * HD / 8; idx += 256) {
        int r = idx >> 4, c = (idx & 15) * 8;
        *(uint4*)&Qh[r * HDP + c] = *(const uint4*)&qh[qoff + r * HD + c];
    }

    const int cr = tid >> 4;
    const int cc = (tid & 15) * 8;

    const int nkt = 2 * qb + 2;

#pragma unroll
    for (int tl = 0; tl < 2; tl++) {
        const size_t gk = hbase + (size_t)tl * BK * HD;
        const uint32_t db = bufb + tl * BUFB;
#pragma unroll
        for (int i = 0; i < 4; i++) {
            int r = cr + i * 16;
            uint32_t d0 = db + (uint32_t)(r * HDP + cc) * 2;
            cp16(d0,        &kh[gk + r * HD + cc]);
            cp16(d0 + ARRB, &vh[gk + r * HD + cc]);
        }
        cp_commit();
    }

    float oacc[16][4];
#pragma unroll
    for (int i = 0; i < 16; i++)
#pragma unroll
        for (int j = 0; j < 4; j++) oacc[i][j] = 0.f;
    float m_a = -1e30f, m_b = -1e30f, l_a = 0.f, l_b = 0.f;

    const int frag  = (l & 7) + 8 * ((l >> 3) & 1);
    const int qvoff = frag * HDP + 8 * (l >> 4);
    const int koff  = ((l & 7) + 8 * (l >> 4)) * HDP + 8 * ((l >> 3) & 1);
    const uint32_t aQh = smb + (uint32_t)(rb * HDP + qvoff) * 2;

    const int row_a = qb * BQ + rb + g;
    const int row_b = row_a + 8;
    const int row_max = qb * BQ + rb + 15;

    for (int kb = 0; kb < nkt; kb++) {
        cp_wait<1>();
        __syncthreads();

        if (kb + 2 < nkt) {
            const size_t gk = hbase + (size_t)(kb + 2) * BK * HD;
            const uint32_t db = bufb + (uint32_t)((kb + 2) % 3) * BUFB;
#pragma unroll
            for (int i = 0; i < 4; i++) {
                int r = cr + i * 16;
                uint32_t d0 = db + (uint32_t)(r * HDP + cc) * 2;
                cp16(d0,        &kh[gk + r * HD + cc]);
                cp16(d0 + ARRB, &vh[gk + r * HD + cc]);
            }
            cp_commit();
        } else {
            cp_commit();
        }

        if (kb * BK <= row_max) {
            const uint32_t cb0 = bufb + (uint32_t)(kb % 3) * BUFB;
            const uint32_t aKh = cb0 + (uint32_t)koff * 2;
            const uint32_t aVh = cb0 + ARRB + (uint32_t)qvoff * 2;

            // ---- S = Q K^T (1-term fp16) ----
            float sacc[8][4];
#pragma unroll
            for (int i = 0; i < 8; i++)
#pragma unroll
                for (int j = 0; j < 4; j++) sacc[i][j] = 0.f;

#pragma unroll
            for (int ks = 0; ks < 8; ks++) {
                uint32_t qhf[4];
                ldsm_x4(qhf, aQh + ks * 32);
#pragma unroll
                for (int np = 0; np < 4; np++) {
                    uint32_t khf[4];
                    ldsm_x4(khf, aKh + np * (16 * HDP * 2) + ks * 32);
                    mma_f16(sacc[2 * np],     qhf, khf[0], khf[1]);
                    mma_f16(sacc[2 * np + 1], qhf, khf[2], khf[3]);
                }
            }

            // ---- causal mask + online softmax (exp2 folded scale) ----
            float mx_a = -1e30f, mx_b = -1e30f;
#pragma unroll
            for (int nt = 0; nt < 8; nt++) {
                int c0 = kb * BK + nt * 8 + 2 * t, c1 = c0 + 1;
                float s0 = sacc[nt][0]; if (c0 > row_a) s0 = -1e30f;
                float s1 = sacc[nt][1]; if (c1 > row_a) s1 = -1e30f;
                float s2 = sacc[nt][2]; if (c0 > row_b) s2 = -1e30f;
                float s3 = sacc[nt][3]; if (c1 > row_b) s3 = -1e30f;
                sacc[nt][0] = s0; sacc[nt][1] = s1; sacc[nt][2] = s2; sacc[nt][3] = s3;
                mx_a = fmaxf(mx_a, fmaxf(s0, s1));
                mx_b = fmaxf(mx_b, fmaxf(s2, s3));
            }
            mx_a = fmaxf(mx_a, __shfl_xor_sync(0xffffffffu, mx_a, 1));
            mx_a = fmaxf(mx_a, __shfl_xor_sync(0xffffffffu, mx_a, 2));
            mx_b = fmaxf(mx_b, __shfl_xor_sync(0xffffffffu, mx_b, 1));
            mx_b = fmaxf(mx_b, __shfl_xor_sync(0xffffffffu, mx_b, 2));

            float mn_a = fmaxf(m_a, mx_a), mn_b = fmaxf(m_b, mx_b);
            float ca = exp2f((m_a - mn_a) * CEXP), cb2 = exp2f((m_b - mn_b) * CEXP);
            m_a = mn_a; m_b = mn_b;

            float sum_a = 0.f, sum_b = 0.f;
            uint32_t pah[4][4];
#pragma unroll
            for (int nt = 0; nt < 8; nt++) {
                float p0 = exp2f((sacc[nt][0] - mn_a) * CEXP);
                float p1 = exp2f((sacc[nt][1] - mn_a) * CEXP);
                float p2 = exp2f((sacc[nt][2] - mn_b) * CEXP);
                float p3 = exp2f((sacc[nt][3] - mn_b) * CEXP);
                sum_a += p0 + p1; sum_b += p2 + p3;
                int ks = nt >> 1, sel = (nt & 1) * 2;
                pah[ks][sel + 0] = pack_h2(p0, p1);
                pah[ks][sel + 1] = pack_h2(p2, p3);
            }
            sum_a += __shfl_xor_sync(0xffffffffu, sum_a, 1);
            sum_a += __shfl_xor_sync(0xffffffffu, sum_a, 2);
            sum_b += __shfl_xor_sync(0xffffffffu, sum_b, 1);
            sum_b += __shfl_xor_sync(0xffffffffu, sum_b, 2);
            l_a = l_a * ca + sum_a;
            l_b = l_b * cb2 + sum_b;

#pragma unroll
            for (int nt = 0; nt < 16; nt++) {
                oacc[nt][0] *= ca;  oacc[nt][1] *= ca;
                oacc[nt][2] *= cb2; oacc[nt][3] *= cb2;
            }

            // ---- O += P_hi * V_hi ----
#pragma unroll
            for (int ks = 0; ks < 4; ks++) {
#pragma unroll
                for (int np = 0; np < 8; np++) {
                    uint32_t vhf[4];
                    ldsm_x4_t(vhf, aVh + ks * (16 * HDP * 2) + np * 32);
                    mma_f16(oacc[2 * np],     pah[ks], vhf[0], vhf[1]);
                    mma_f16(oacc[2 * np + 1], pah[ks], vhf[2], vhf[3]);
                }
            }
        }
        __syncthreads();
    }

    // ---- epilogue: half O out ----
    float ia = 1.f / l_a, ib = 1.f / l_b;
    __half* outa = go + (size_t)row_a * OD + h * HD;
    __half* outb = outa + (size_t)8 * OD;
#pragma unroll
    for (int nt = 0; nt < 16; nt++) {
        *(uint32_t*)&outa[nt * 8 + 2 * t] = pack_h2(oacc[nt][0] * ia, oacc[nt][1] * ia);
        *(uint32_t*)&outb[nt * 8 + 2 * t] = pack_h2(oacc[nt][2] * ib, oacc[nt][3] * ib);
    }
}

// ---------------- launch -----------------------------------------------------
extern "C" void kernel_launch(void* const* d_in, const int* in_sizes, int n_in,
                              void* d_out, int out_size)
{
    const float* hidden    = (const float*)d_in[0];
    const int*   positions = (const int*)  d_in[1];
    const float* qkv_w     = (const float*)d_in[2];
    const float* q_norm_w  = (const float*)d_in[3];
    const float* k_norm_w  = (const float*)d_in[4];
    const float* o_proj_w  = (const float*)d_in[5];
    float* out = (float*)d_out;

    float *p_qkv;
    __half *p_qh, *p_kh, *p_vh, *p_oh, *p_hh, *p_wq, *p_wo;
    cudaGetSymbolAddress((void**)&p_qkv, g_qkv);
    cudaGetSymbolAddress((void**)&p_qh,  g_qh);
    cudaGetSymbolAddress((void**)&p_kh,  g_kh);
    cudaGetSymbolAddress((void**)&p_vh,  g_vh);
    cudaGetSymbolAddress((void**)&p_oh,  g_oh);
    cudaGetSymbolAddress((void**)&p_hh,  g_hh);
    cudaGetSymbolAddress((void**)&p_wq,  g_wq);
    cudaGetSymbolAddress((void**)&p_wo,  g_wo);

    cudaFuncSetAttribute(attn_mma, cudaFuncAttributeMaxDynamicSharedMemorySize, ATTN_SMEM);
    cudaFuncSetAttribute(gemm_h,   cudaFuncAttributeMaxDynamicSharedMemorySize, GEMMH_SMEM);

    // 0) conversions + rope table
    {
        int n1 = S_LEN * HIDDEN;
        f2h<<<n1 / 1024, 256>>>(hidden, p_hh, n1);
        int n2 = QKV_N * HIDDEN;
        f2h<<<n2 / 1024, 256>>>(qkv_w, p_wq, n2);
        int n3 = HIDDEN * OD;
        f2h<<<n3 / 1024, 256>>>(o_proj_w, p_wo, n3);
        rope_table<<<S_LEN, 64>>>(positions);
    }

    // 1) QKV GEMM (half inputs)
    gemm_h<<<dim3(QKV_N / 128, S_LEN / 128), 256, GEMMH_SMEM>>>(p_hh, p_wq, p_qkv,
                                                                S_LEN, QKV_N, HIDDEN);

    // 2) RMSNorm + RoPE (table) + fp16 scatter
    norm_rope<<<dim3(HEADS, S_LEN), 128>>>(p_qkv, q_norm_w, k_norm_w);

    // 3) tensor-core causal flash attention (1-term fp16)
    attn_mma<<<dim3(S_LEN / BQ, HEADS), 256, ATTN_SMEM>>>(p_qh, p_kh, p_vh, p_oh);

    // 4) O projection (half inputs)
    gemm_h<<<dim3(HIDDEN / 128, S_LEN / 128), 256, GEMMH_SMEM>>>(p_oh, p_wo, out,
                                                                 S_LEN, HIDDEN, OD);
}